// round 15
// baseline (speedup 1.0000x reference)
#include <cuda_runtime.h>
#include <cstdint>

// ============================================================================
// CustomLoss fused reduction — FINAL (R11 configuration, measured optimum)
//
// 96 MB pure-streaming reduction over 5 input streams -> 1 scalar.
// Design (each element validated by a bench round):
//  - Single kernel, one wave: 740 blocks = 148 SMs x 5 CTAs, 256 threads.
//  - occ=5 -> 48 regs: keeps the 5-load front batch fully in flight (MLP=5);
//    measured optimum of the occupancy sweep (24/32/40/48 warps per SM).
//  - Balanced contiguous partition (per-SM bytes uniform to <0.1%).
//  - 1 x LDG.E.256 (pred) + 4 x LDG.E.128 per iteration, front-batched.
//  - Tail: per-block Q32 fixed-point atomics (exactly associative ->
//    deterministic across graph replays); last-arriving block finishes the
//    scalar in-kernel. No second launch, no serial partial scan.
// ============================================================================

#define B_ELEMS 4194304          // 2^22 samples
#define NBLK    740              // 148 SMs * 5 CTAs -> one wave at occ 5
#define NTH     256
#define NVEC    (B_ELEMS / 4)    // 2^20 vec4 groups
#define VB_BASE (NVEC / NBLK)    // base vec4 per block
#define VB_REM  (NVEC % NBLK)    // first VB_REM blocks take one extra

// Fixed-point (Q32) global accumulators: [center, width, valid, dir]
__device__ unsigned long long g_acc[4] = {0ull, 0ull, 0ull, 0ull};
__device__ unsigned int       g_count  = 0;

#define FP_SCALE 4294967296.0    // 2^32

// 256-bit global load (sm_100+): pred's two adjacent float4 in one LDG.E.256.
__device__ __forceinline__ void ldg_v8f(const float* __restrict__ p, float r[8]) {
    asm volatile("ld.global.v8.f32 {%0,%1,%2,%3,%4,%5,%6,%7}, [%8];"
                 : "=f"(r[0]), "=f"(r[1]), "=f"(r[2]), "=f"(r[3]),
                   "=f"(r[4]), "=f"(r[5]), "=f"(r[6]), "=f"(r[7])
                 : "l"(p));
}

__device__ __forceinline__ void accum_one(float lower, float upper,
                                          float tgt, float prev,
                                          int dt, int pv,
                                          float& s_center, float& s_width,
                                          float& s_valid, float& s_dir) {
    float center = (lower + upper) * 0.5f;
    float d = tgt - center;
    s_center = fmaf(d, d, s_center);
    s_width += (upper - lower);
    s_valid += fmaxf(lower - upper, 0.0f);
    float diff = center - prev;               // pen_up = relu(diff), pen_dn = relu(-diff)
    float sel = (pv == 0) ? diff : -diff;
    s_dir += (dt != 0) ? fmaxf(sel, 0.0f) : 0.0f;
}

__global__ void __launch_bounds__(NTH, 5)
loss_fused_kernel(const float*  __restrict__ pred,   // (B,2) row-major
                  const float4* __restrict__ target, // B/4 float4
                  const float4* __restrict__ prev,   // B/4 float4
                  const int4*   __restrict__ dt,     // B/4 int4
                  const int4*   __restrict__ pv,     // B/4 int4
                  float* __restrict__ out)
{
    float s_center = 0.f, s_width = 0.f, s_valid = 0.f, s_dir = 0.f;

    const int b     = blockIdx.x;
    const int start = b * VB_BASE + (b < VB_REM ? b : VB_REM);
    const int end   = start + VB_BASE + (b < VB_REM ? 1 : 0);

    for (int v = start + threadIdx.x; v < end; v += NTH) {
        // 5 front-batched loads: 1 x 256-bit (pred, samples 4v..4v+3) + 4 x 128-bit
        float p[8];
        ldg_v8f(pred + 8 * v, p);                  // (l0,u0,l1,u1,l2,u2,l3,u3)
        float4 t  = target[v];
        float4 pc = prev[v];
        int4   d  = dt[v];
        int4   q  = pv[v];

        accum_one(p[0], p[1], t.x, pc.x, d.x, q.x, s_center, s_width, s_valid, s_dir);
        accum_one(p[2], p[3], t.y, pc.y, d.y, q.y, s_center, s_width, s_valid, s_dir);
        accum_one(p[4], p[5], t.z, pc.z, d.z, q.z, s_center, s_width, s_valid, s_dir);
        accum_one(p[6], p[7], t.w, pc.w, d.w, q.w, s_center, s_width, s_valid, s_dir);
    }

    // ---- intra-block reduce (float) ----
    #pragma unroll
    for (int off = 16; off > 0; off >>= 1) {
        s_center += __shfl_down_sync(0xFFFFFFFFu, s_center, off);
        s_width  += __shfl_down_sync(0xFFFFFFFFu, s_width,  off);
        s_valid  += __shfl_down_sync(0xFFFFFFFFu, s_valid,  off);
        s_dir    += __shfl_down_sync(0xFFFFFFFFu, s_dir,    off);
    }

    __shared__ float sh[4][NTH / 32];
    int lane = threadIdx.x & 31;
    int warp = threadIdx.x >> 5;
    if (lane == 0) {
        sh[0][warp] = s_center;
        sh[1][warp] = s_width;
        sh[2][warp] = s_valid;
        sh[3][warp] = s_dir;
    }
    __syncthreads();

    if (threadIdx.x == 0) {
        float c = 0.f, w = 0.f, vd = 0.f, dr = 0.f;
        #pragma unroll
        for (int i = 0; i < NTH / 32; i++) {
            c  += sh[0][i];
            w  += sh[1][i];
            vd += sh[2][i];
            dr += sh[3][i];
        }
        // Deterministic fixed-point accumulation (Q32)
        long long ic = __double2ll_rn((double)c  * FP_SCALE);
        long long iw = __double2ll_rn((double)w  * FP_SCALE);
        long long iv = __double2ll_rn((double)vd * FP_SCALE);
        long long id = __double2ll_rn((double)dr * FP_SCALE);
        atomicAdd(&g_acc[0], (unsigned long long)ic);
        atomicAdd(&g_acc[1], (unsigned long long)iw);
        atomicAdd(&g_acc[2], (unsigned long long)iv);
        atomicAdd(&g_acc[3], (unsigned long long)id);
        __threadfence();
        unsigned int prev_cnt = atomicAdd(&g_count, 1u);
        if (prev_cnt == (unsigned int)(NBLK - 1)) {
            // Last block: finish the scalar, reset state for next replay
            __threadfence();
            double fc = (double)(long long)g_acc[0] / FP_SCALE;
            double fw = (double)(long long)g_acc[1] / FP_SCALE;
            double fv = (double)(long long)g_acc[2] / FP_SCALE;
            double fd = (double)(long long)g_acc[3] / FP_SCALE;
            const double invn = 1.0 / (double)B_ELEMS;
            double total = (fc * invn) * 1.5 + 0.1 * (fw * invn)
                         + 10.0 * (fv * invn) + 0.5 * fd * invn;
            out[0] = (float)total;
            g_acc[0] = 0ull;
            g_acc[1] = 0ull;
            g_acc[2] = 0ull;
            g_acc[3] = 0ull;
            g_count  = 0;
        }
    }
}

extern "C" void kernel_launch(void* const* d_in, const int* in_sizes, int n_in,
                              void* d_out, int out_size) {
    const float*  pred   = (const float*)d_in[0];
    const float4* target = (const float4*)d_in[1];
    const float4* prev   = (const float4*)d_in[2];
    const int4*   dt     = (const int4*)d_in[3];
    const int4*   pv     = (const int4*)d_in[4];
    float* out = (float*)d_out;

    loss_fused_kernel<<<NBLK, NTH>>>(pred, target, prev, dt, pv, out);
}

// round 16
// speedup vs baseline: 1.0151x; 1.0151x over previous
#include <cuda_runtime.h>
#include <cstdint>

// ============================================================================
// CustomLoss fused reduction — R11 config + parallelized epilogue atomics.
//  - 740 blocks x 256 thr (148 SMs x 5 CTAs, one wave), occ 5 -> 48 regs.
//  - 1 x LDG.E.256 (pred) + 4 x LDG.E.128 per iter, front-batched (MLP=5).
//  - Balanced contiguous partition; deterministic Q32 fixed-point atomics;
//    last-arriving block finishes the scalar in-kernel.
//  - Epilogue: lanes 0-3 of warp 0 each own one loss component -> the 4
//    global atomics issue in parallel instead of serialized in thread 0.
// ============================================================================

#define B_ELEMS 4194304          // 2^22 samples
#define NBLK    740              // 148 SMs * 5 CTAs -> one wave at occ 5
#define NTH     256
#define NVEC    (B_ELEMS / 4)    // 2^20 vec4 groups
#define VB_BASE (NVEC / NBLK)    // base vec4 per block
#define VB_REM  (NVEC % NBLK)    // first VB_REM blocks take one extra

// Fixed-point (Q32) global accumulators: [center, width, valid, dir]
__device__ unsigned long long g_acc[4] = {0ull, 0ull, 0ull, 0ull};
__device__ unsigned int       g_count  = 0;

#define FP_SCALE 4294967296.0    // 2^32

// 256-bit global load (sm_100+): pred's two adjacent float4 in one LDG.E.256.
__device__ __forceinline__ void ldg_v8f(const float* __restrict__ p, float r[8]) {
    asm volatile("ld.global.v8.f32 {%0,%1,%2,%3,%4,%5,%6,%7}, [%8];"
                 : "=f"(r[0]), "=f"(r[1]), "=f"(r[2]), "=f"(r[3]),
                   "=f"(r[4]), "=f"(r[5]), "=f"(r[6]), "=f"(r[7])
                 : "l"(p));
}

__device__ __forceinline__ void accum_one(float lower, float upper,
                                          float tgt, float prev,
                                          int dt, int pv,
                                          float& s_center, float& s_width,
                                          float& s_valid, float& s_dir) {
    float center = (lower + upper) * 0.5f;
    float d = tgt - center;
    s_center = fmaf(d, d, s_center);
    s_width += (upper - lower);
    s_valid += fmaxf(lower - upper, 0.0f);
    float diff = center - prev;               // pen_up = relu(diff), pen_dn = relu(-diff)
    float sel = (pv == 0) ? diff : -diff;
    s_dir += (dt != 0) ? fmaxf(sel, 0.0f) : 0.0f;
}

__global__ void __launch_bounds__(NTH, 5)
loss_fused_kernel(const float*  __restrict__ pred,   // (B,2) row-major
                  const float4* __restrict__ target, // B/4 float4
                  const float4* __restrict__ prev,   // B/4 float4
                  const int4*   __restrict__ dt,     // B/4 int4
                  const int4*   __restrict__ pv,     // B/4 int4
                  float* __restrict__ out)
{
    float s_center = 0.f, s_width = 0.f, s_valid = 0.f, s_dir = 0.f;

    const int b     = blockIdx.x;
    const int start = b * VB_BASE + (b < VB_REM ? b : VB_REM);
    const int end   = start + VB_BASE + (b < VB_REM ? 1 : 0);

    for (int v = start + threadIdx.x; v < end; v += NTH) {
        // 5 front-batched loads: 1 x 256-bit (pred, samples 4v..4v+3) + 4 x 128-bit
        float p[8];
        ldg_v8f(pred + 8 * v, p);                  // (l0,u0,l1,u1,l2,u2,l3,u3)
        float4 t  = target[v];
        float4 pc = prev[v];
        int4   d  = dt[v];
        int4   q  = pv[v];

        accum_one(p[0], p[1], t.x, pc.x, d.x, q.x, s_center, s_width, s_valid, s_dir);
        accum_one(p[2], p[3], t.y, pc.y, d.y, q.y, s_center, s_width, s_valid, s_dir);
        accum_one(p[4], p[5], t.z, pc.z, d.z, q.z, s_center, s_width, s_valid, s_dir);
        accum_one(p[6], p[7], t.w, pc.w, d.w, q.w, s_center, s_width, s_valid, s_dir);
    }

    // ---- intra-block reduce (float) ----
    #pragma unroll
    for (int off = 16; off > 0; off >>= 1) {
        s_center += __shfl_down_sync(0xFFFFFFFFu, s_center, off);
        s_width  += __shfl_down_sync(0xFFFFFFFFu, s_width,  off);
        s_valid  += __shfl_down_sync(0xFFFFFFFFu, s_valid,  off);
        s_dir    += __shfl_down_sync(0xFFFFFFFFu, s_dir,    off);
    }

    __shared__ float sh[4][NTH / 32];
    int lane = threadIdx.x & 31;
    int warp = threadIdx.x >> 5;
    if (lane == 0) {
        sh[0][warp] = s_center;
        sh[1][warp] = s_width;
        sh[2][warp] = s_valid;
        sh[3][warp] = s_dir;
    }
    __syncthreads();

    if (warp == 0) {
        // Lanes 0-3 each own one component: sum 8 warp-partials, fire atomic.
        if (lane < 4) {
            float acc = 0.f;
            #pragma unroll
            for (int i = 0; i < NTH / 32; i++)
                acc += sh[lane][i];
            long long fx = __double2ll_rn((double)acc * FP_SCALE);
            atomicAdd(&g_acc[lane], (unsigned long long)fx);
        }
        __syncwarp();

        if (lane == 0) {
            __threadfence();
            unsigned int prev_cnt = atomicAdd(&g_count, 1u);
            if (prev_cnt == (unsigned int)(NBLK - 1)) {
                // Last block: finish the scalar, reset state for next replay
                __threadfence();
                double fc = (double)(long long)g_acc[0] / FP_SCALE;
                double fw = (double)(long long)g_acc[1] / FP_SCALE;
                double fv = (double)(long long)g_acc[2] / FP_SCALE;
                double fd = (double)(long long)g_acc[3] / FP_SCALE;
                const double invn = 1.0 / (double)B_ELEMS;
                double total = (fc * invn) * 1.5 + 0.1 * (fw * invn)
                             + 10.0 * (fv * invn) + 0.5 * fd * invn;
                out[0] = (float)total;
                g_acc[0] = 0ull;
                g_acc[1] = 0ull;
                g_acc[2] = 0ull;
                g_acc[3] = 0ull;
                g_count  = 0;
            }
        }
    }
}

extern "C" void kernel_launch(void* const* d_in, const int* in_sizes, int n_in,
                              void* d_out, int out_size) {
    const float*  pred   = (const float*)d_in[0];
    const float4* target = (const float4*)d_in[1];
    const float4* prev   = (const float4*)d_in[2];
    const int4*   dt     = (const int4*)d_in[3];
    const int4*   pv     = (const int4*)d_in[4];
    float* out = (float*)d_out;

    loss_fused_kernel<<<NBLK, NTH>>>(pred, target, prev, dt, pv, out);
}

// round 17
// speedup vs baseline: 1.0375x; 1.0221x over previous
#include <cuda_runtime.h>
#include <cstdint>

// ============================================================================
// CustomLoss fused reduction — FINAL.
// 96 MB pure-streaming reduction over 5 input streams -> 1 scalar, pinned at
// the DRAM roofline (~6.9 TB/s end-to-end incl. launch overhead).
//
// Design, each element validated by a bench round (23.3 us -> 14.6 us):
//  - Single kernel, one wave: 740 blocks = 148 SMs x 5 CTAs, 256 threads.
//    occ=5 -> 48 regs: measured optimum (occ 3/4/5/6 and 128-thr CTAs swept).
//  - 5 front-batched loads per iter: 1 x LDG.E.256 (pred) + 4 x LDG.E.128,
//    all live simultaneously (MLP=5).
//  - Balanced contiguous partition: per-SM bytes uniform to <0.1%.
//  - Tail: per-block Q32 fixed-point global atomics (exactly associative ->
//    deterministic across graph replays); lanes 0-3 fire the 4 component
//    atomics in parallel; last-arriving block finishes the scalar in-kernel
//    and resets state. No second launch, no serial partial scan.
// ============================================================================

#define B_ELEMS 4194304          // 2^22 samples
#define NBLK    740              // 148 SMs * 5 CTAs -> one wave at occ 5
#define NTH     256
#define NVEC    (B_ELEMS / 4)    // 2^20 vec4 groups
#define VB_BASE (NVEC / NBLK)    // base vec4 per block
#define VB_REM  (NVEC % NBLK)    // first VB_REM blocks take one extra

// Fixed-point (Q32) global accumulators: [center, width, valid, dir]
__device__ unsigned long long g_acc[4] = {0ull, 0ull, 0ull, 0ull};
__device__ unsigned int       g_count  = 0;

#define FP_SCALE 4294967296.0    // 2^32

// 256-bit global load (sm_100+): pred's two adjacent float4 in one LDG.E.256.
__device__ __forceinline__ void ldg_v8f(const float* __restrict__ p, float r[8]) {
    asm volatile("ld.global.v8.f32 {%0,%1,%2,%3,%4,%5,%6,%7}, [%8];"
                 : "=f"(r[0]), "=f"(r[1]), "=f"(r[2]), "=f"(r[3]),
                   "=f"(r[4]), "=f"(r[5]), "=f"(r[6]), "=f"(r[7])
                 : "l"(p));
}

__device__ __forceinline__ void accum_one(float lower, float upper,
                                          float tgt, float prev,
                                          int dt, int pv,
                                          float& s_center, float& s_width,
                                          float& s_valid, float& s_dir) {
    float center = (lower + upper) * 0.5f;
    float d = tgt - center;
    s_center = fmaf(d, d, s_center);
    s_width += (upper - lower);
    s_valid += fmaxf(lower - upper, 0.0f);
    float diff = center - prev;               // pen_up = relu(diff), pen_dn = relu(-diff)
    float sel = (pv == 0) ? diff : -diff;
    s_dir += (dt != 0) ? fmaxf(sel, 0.0f) : 0.0f;
}

__global__ void __launch_bounds__(NTH, 5)
loss_fused_kernel(const float*  __restrict__ pred,   // (B,2) row-major
                  const float4* __restrict__ target, // B/4 float4
                  const float4* __restrict__ prev,   // B/4 float4
                  const int4*   __restrict__ dt,     // B/4 int4
                  const int4*   __restrict__ pv,     // B/4 int4
                  float* __restrict__ out)
{
    float s_center = 0.f, s_width = 0.f, s_valid = 0.f, s_dir = 0.f;

    const int b     = blockIdx.x;
    const int start = b * VB_BASE + (b < VB_REM ? b : VB_REM);
    const int end   = start + VB_BASE + (b < VB_REM ? 1 : 0);

    for (int v = start + threadIdx.x; v < end; v += NTH) {
        // 5 front-batched loads: 1 x 256-bit (pred, samples 4v..4v+3) + 4 x 128-bit
        float p[8];
        ldg_v8f(pred + 8 * v, p);                  // (l0,u0,l1,u1,l2,u2,l3,u3)
        float4 t  = target[v];
        float4 pc = prev[v];
        int4   d  = dt[v];
        int4   q  = pv[v];

        accum_one(p[0], p[1], t.x, pc.x, d.x, q.x, s_center, s_width, s_valid, s_dir);
        accum_one(p[2], p[3], t.y, pc.y, d.y, q.y, s_center, s_width, s_valid, s_dir);
        accum_one(p[4], p[5], t.z, pc.z, d.z, q.z, s_center, s_width, s_valid, s_dir);
        accum_one(p[6], p[7], t.w, pc.w, d.w, q.w, s_center, s_width, s_valid, s_dir);
    }

    // ---- intra-block reduce (float) ----
    #pragma unroll
    for (int off = 16; off > 0; off >>= 1) {
        s_center += __shfl_down_sync(0xFFFFFFFFu, s_center, off);
        s_width  += __shfl_down_sync(0xFFFFFFFFu, s_width,  off);
        s_valid  += __shfl_down_sync(0xFFFFFFFFu, s_valid,  off);
        s_dir    += __shfl_down_sync(0xFFFFFFFFu, s_dir,    off);
    }

    __shared__ float sh[4][NTH / 32];
    int lane = threadIdx.x & 31;
    int warp = threadIdx.x >> 5;
    if (lane == 0) {
        sh[0][warp] = s_center;
        sh[1][warp] = s_width;
        sh[2][warp] = s_valid;
        sh[3][warp] = s_dir;
    }
    __syncthreads();

    if (warp == 0) {
        // Lanes 0-3 each own one component: sum 8 warp-partials, fire atomic.
        if (lane < 4) {
            float acc = 0.f;
            #pragma unroll
            for (int i = 0; i < NTH / 32; i++)
                acc += sh[lane][i];
            long long fx = __double2ll_rn((double)acc * FP_SCALE);
            atomicAdd(&g_acc[lane], (unsigned long long)fx);
        }
        __syncwarp();

        if (lane == 0) {
            __threadfence();
            unsigned int prev_cnt = atomicAdd(&g_count, 1u);
            if (prev_cnt == (unsigned int)(NBLK - 1)) {
                // Last block: finish the scalar, reset state for next replay
                __threadfence();
                double fc = (double)(long long)g_acc[0] / FP_SCALE;
                double fw = (double)(long long)g_acc[1] / FP_SCALE;
                double fv = (double)(long long)g_acc[2] / FP_SCALE;
                double fd = (double)(long long)g_acc[3] / FP_SCALE;
                const double invn = 1.0 / (double)B_ELEMS;
                double total = (fc * invn) * 1.5 + 0.1 * (fw * invn)
                             + 10.0 * (fv * invn) + 0.5 * fd * invn;
                out[0] = (float)total;
                g_acc[0] = 0ull;
                g_acc[1] = 0ull;
                g_acc[2] = 0ull;
                g_acc[3] = 0ull;
                g_count  = 0;
            }
        }
    }
}

extern "C" void kernel_launch(void* const* d_in, const int* in_sizes, int n_in,
                              void* d_out, int out_size) {
    const float*  pred   = (const float*)d_in[0];
    const float4* target = (const float4*)d_in[1];
    const float4* prev   = (const float4*)d_in[2];
    const int4*   dt     = (const int4*)d_in[3];
    const int4*   pv     = (const int4*)d_in[4];
    float* out = (float*)d_out;

    loss_fused_kernel<<<NBLK, NTH>>>(pred, target, prev, dt, pv, out);
}